// round 16
// baseline (speedup 1.0000x reference)
#include <cuda_runtime.h>
#include <math.h>

#define Bc 256
#define Vc 4096
#define Kc 64
#define MINIf 1e-6f

#define VK (Vc*Kc)             /* 262144 */
#define BK (Bc*Kc)             /* 16384  */
#define OUT_TN 0
#define OUT_TM VK
#define OUT_QZ (VK+BK)
#define OUT_NN (VK+BK+1)
#define OUT_NM (VK+BK+1+VK)

#define NBLK 256

// device scratch — float4-accessed arrays explicitly 16B-aligned
__device__ __align__(16) float g_theta[BK];   // theta' published by x==0 blocks
__device__ __align__(16) float g_Nacc[VK];    // self-reset in epilogue
__device__ __align__(16) float g_Macc[BK];    // self-reset in epilogue
__device__ __align__(16) float g_denom[Kc];   // self-reset post-bar1
__device__ unsigned g_barcnt[2];              // monotone epoch counters
__device__ unsigned g_barrel[2];
__device__ float g_rho;
__device__ float g_ratio;

// ---- packed f32x2 helpers (Blackwell FFMA2) --------------------------------
__device__ __forceinline__ void pfma(unsigned long long& acc,
                                     unsigned long long a, unsigned long long b) {
    asm("fma.rn.f32x2 %0, %1, %2, %0;" : "+l"(acc) : "l"(a), "l"(b));
}
__device__ __forceinline__ float psum(unsigned long long v) {
    return __uint_as_float((unsigned)v) + __uint_as_float((unsigned)(v >> 32));
}
__device__ __forceinline__ unsigned long long fpack2(float lo, float hi) {
    unsigned long long r;
    asm("mov.b64 %0, {%1, %2};" : "=l"(r) : "f"(lo), "f"(hi));
    return r;
}
__device__ __forceinline__ void punpack(unsigned long long v, float& lo, float& hi) {
    lo = __uint_as_float((unsigned)v);
    hi = __uint_as_float((unsigned)(v >> 32));
}

// ---- split grid barrier (epoch-monotone; replay-safe) -----------------------
__device__ __forceinline__ unsigned bar_arrive(int id) {
    __syncthreads();
    __shared__ unsigned s_ep[2];
    if (threadIdx.x == 0) {
        __threadfence();
        unsigned arrive = atomicAdd(&g_barcnt[id], 1u) + 1u;
        unsigned epoch = (arrive + NBLK - 1u) / NBLK;
        if (arrive == epoch * NBLK)
            atomicAdd(&g_barrel[id], 1u);
        s_ep[id] = epoch;
    }
    __syncthreads();
    return s_ep[id];
}
__device__ __forceinline__ void bar_wait(int id, unsigned epoch) {
    if (threadIdx.x == 0) {
        while (atomicAdd(&g_barrel[id], 0u) < epoch) __nanosleep(64);
    }
    __syncthreads();
}

// ---------------------------------------------------------------------------
__global__ void __launch_bounds__(256, 2)
mono(const int* __restrict__ bow,
     const unsigned int* __restrict__ idxw,
     const float* __restrict__ alpha,
     const float* __restrict__ pi,
     const float* __restrict__ expm,
     const float* __restrict__ beta,
     const float* __restrict__ expn,
     const int* __restrict__ iterp,
     const int* __restrict__ cmp,
     const int* __restrict__ bcp,
     float* __restrict__ out) {
    extern __shared__ float sm3[];
    float (*th)[68]  = (float(*)[68])(sm3);
    float (*thL)[68] = (float(*)[68])(sm3 + 64 * 68);
    float (*ph)[68]  = (float(*)[68])(sm3 + 128 * 68);
    float (*phL)[68] = (float(*)[68])(sm3 + 192 * 68);
    // pre-packed W: u64 (w,w) per element, row-major [b][v], pitch 66 u64
    unsigned long long (*W2)[66] =
        (unsigned long long (*)[66])(sm3 + 256 * 68);

    __shared__ __align__(16) float red[16][68];
    __shared__ __align__(16) float srd[64];
    __shared__ __align__(16) float sld[64];
    __shared__ float ered[8];
    __shared__ int s_nz;

    int t = threadIdx.x;
    int rank = blockIdx.y * 64 + blockIdx.x;
    int v0 = blockIdx.x * 64;
    int b0 = blockIdx.y * 64;
    int tv = t & 15;       // v_local = tv + 16*vi
    int tb = t >> 4;       // b_local = tb + 16*bi

    // ---- phase 0: bow prefetch (packed: counts fit 8 bits) + denom partial --
    unsigned long long cp0 = 0ull, cp1 = 0ull;
    #pragma unroll
    for (int bi = 0; bi < 4; ++bi)
        #pragma unroll
        for (int vi = 0; vi < 4; ++vi) {
            int c = bow[(b0 + tb + 16 * bi) * Vc + v0 + tv + 16 * vi];
            int idx = bi * 4 + vi;
            if (idx < 8) cp0 |= (unsigned long long)(c & 255) << (idx * 8);
            else         cp1 |= (unsigned long long)(c & 255) << ((idx - 8) * 8);
        }

    if (t == 0) s_nz = 0;
    {
        int cq = t & 15, rr = t >> 4;
        int vp = rank * 16;
        float4 db = ((const float4*)beta)[(vp + rr) * 16 + cq];
        float4 de = ((const float4*)expn)[(vp + rr) * 16 + cq];
        __syncthreads();                       // s_nz init visible
        if (t < 128 && idxw[2 * t + 1] != 0u) atomicOr(&s_nz, 1);
        float4 a;
        a.x = db.x + de.x; a.y = db.y + de.y;
        a.z = db.z + de.z; a.w = db.w + de.w;
        *(float4*)&red[rr][cq * 4] = a;
        __syncthreads();
        if (t < 64) {
            float s = 0.f;
            #pragma unroll
            for (int r2 = 0; r2 < 16; ++r2) s += red[r2][t];
            atomicAdd(&g_denom[t], s);
        }
        if (rank == 255 && t == 0) {
            g_rho   = 1.f / powf((float)(iterp[0] + 5), 0.9f);
            g_ratio = (float)cmp[0] / (float)bcp[0];
            out[OUT_QZ] = 0.f;
        }
    }
    int stride = s_nz ? 1 : 2;    // int32 vs int64 batch_indices

    // ---- bar0 ARRIVE early (skew absorbed by log-heavy fill) ----
    unsigned ep0 = bar_arrive(0);

    // tile fill (NO denominator needed)
    #pragma unroll
    for (int j = 0; j < 4; ++j) {
        int i = j * 256 + t;
        int r = i >> 4, cq = i & 15;
        float4 b4 = ((const float4*)beta)[(v0 + r) * 16 + cq];
        float4 e4 = ((const float4*)expn)[(v0 + r) * 16 + cq];
        float4 p;
        p.x = b4.x + e4.x; p.y = b4.y + e4.y;
        p.z = b4.z + e4.z; p.w = b4.w + e4.w;
        float4 pl;
        pl.x = p.x * __logf(p.x);
        pl.y = p.y * __logf(p.y);
        pl.z = p.z * __logf(p.z);
        pl.w = p.w * __logf(p.w);
        *(float4*)&ph [r][cq * 4] = p;
        *(float4*)&phL[r][cq * 4] = pl;
        int d = (int)idxw[(b0 + r) * stride];
        float4 al = ((const float4*)alpha)[cq];
        float4 pp = ((const float4*)pi   )[d * 16 + cq];
        float4 em = ((const float4*)expm )[d * 16 + cq];
        float4 traw, tl;
        traw.x = fmaf(al.x, pp.x, em.x);
        traw.y = fmaf(al.y, pp.y, em.y);
        traw.z = fmaf(al.z, pp.z, em.z);
        traw.w = fmaf(al.w, pp.w, em.w);
        tl.x = traw.x * __logf(traw.x);
        tl.y = traw.y * __logf(traw.y);
        tl.z = traw.z * __logf(traw.z);
        tl.w = traw.w * __logf(traw.w);
        *(float4*)&th [r][cq * 4] = traw;
        *(float4*)&thL[r][cq * 4] = tl;
    }

    // ---- bar0 WAIT ----
    bar_wait(0, ep0);

    if (t < 64) {
        float d = g_denom[t];
        srd[t] = __fdividef(1.f, d);
        sld[t] = __logf(d);
    }
    __syncthreads();

    // scale theta tiles: th' = traw*rd ; thL' = (trawL - traw*ld)*rd
    #pragma unroll
    for (int j = 0; j < 4; ++j) {
        int i = j * 256 + t;
        int r = i >> 4, cq = i & 15;
        float4 tp  = *(const float4*)&th [r][cq * 4];
        float4 tlp = *(const float4*)&thL[r][cq * 4];
        float4 rd = *(const float4*)&srd[cq * 4];
        float4 ld = *(const float4*)&sld[cq * 4];
        float4 tt, tl;
        tt.x = tp.x * rd.x; tt.y = tp.y * rd.y;
        tt.z = tp.z * rd.z; tt.w = tp.w * rd.w;
        tl.x = (tlp.x - tp.x * ld.x) * rd.x;
        tl.y = (tlp.y - tp.y * ld.y) * rd.y;
        tl.z = (tlp.z - tp.z * ld.z) * rd.z;
        tl.w = (tlp.w - tp.w * ld.w) * rd.w;
        *(float4*)&th [r][cq * 4] = tt;
        *(float4*)&thL[r][cq * 4] = tl;
        if (blockIdx.x == 0)
            ((float4*)g_theta)[(b0 + r) * 16 + cq] = tt;
    }
    __syncthreads();

    // ---- phase 1: S/A GEMM ----
    unsigned long long S2[4][4], A2[4][4];
    #pragma unroll
    for (int bi = 0; bi < 4; ++bi)
        #pragma unroll
        for (int vi = 0; vi < 4; ++vi) { S2[bi][vi] = 0ull; A2[bi][vi] = 0ull; }

    #pragma unroll 4
    for (int kq = 0; kq < 16; ++kq) {
        ulonglong2 P[4], Q[4];
        #pragma unroll
        for (int vi = 0; vi < 4; ++vi) {
            P[vi] = *(const ulonglong2*)&ph [tv + 16 * vi][kq * 4];
            Q[vi] = *(const ulonglong2*)&phL[tv + 16 * vi][kq * 4];
        }
        #pragma unroll
        for (int bi = 0; bi < 4; ++bi) {
            ulonglong2 T = *(const ulonglong2*)&th [tb + 16 * bi][kq * 4];
            ulonglong2 L = *(const ulonglong2*)&thL[tb + 16 * bi][kq * 4];
            #pragma unroll
            for (int vi = 0; vi < 4; ++vi) {
                pfma(S2[bi][vi], T.x, P[vi].x);
                pfma(S2[bi][vi], T.y, P[vi].y);
                pfma(A2[bi][vi], L.x, P[vi].x);
                pfma(A2[bi][vi], L.y, P[vi].y);
                pfma(A2[bi][vi], T.x, Q[vi].x);
                pfma(A2[bi][vi], T.y, Q[vi].y);
            }
        }
    }

    // w, entropy; write pre-packed W2 = (w,w)
    float ent = 0.f;
    unsigned long long wp[4][4];
    #pragma unroll
    for (int bi = 0; bi < 4; ++bi) {
        #pragma unroll
        for (int vi = 0; vi < 4; ++vi) {
            float S = psum(S2[bi][vi]);
            float A = psum(A2[bi][vi]);
            float sp = S + MINIf;
            float r  = __fdividef(1.f, sp);
            int idx = bi * 4 + vi;
            int c = (int)(((idx < 8 ? cp0 : cp1) >> ((idx & 7) * 8)) & 255ull);
            float w = (float)c * r;
            wp[bi][vi] = fpack2(w, w);
            if (c > 0)
                ent += (A - S * __logf(sp)) * r;
        }
    }

    #pragma unroll
    for (int o = 16; o; o >>= 1)
        ent += __shfl_xor_sync(0xFFFFFFFFu, ent, o);
    if ((t & 31) == 0) ered[t >> 5] = ent;

    __syncthreads();
    if (t == 0) {
        float s = 0.f;
        #pragma unroll
        for (int w = 0; w < 8; ++w) s += ered[w];
        atomicAdd(&out[OUT_QZ], s);
    }

    #pragma unroll
    for (int bi = 0; bi < 4; ++bi)
        #pragma unroll
        for (int vi = 0; vi < 4; ++vi)
            W2[tb + 16 * bi][tv + 16 * vi] = wp[bi][vi];
    __syncthreads();

    // ---- phase 2 (pre-packed W: no fpack2, fewer issues) ----
    int kq2 = t & 15;
    int tr  = t >> 4;

    // 2a: Macc[b,k] += sum_v W2[b][v] * ph[v][k]
    {
        unsigned long long acc[4][2];
        #pragma unroll
        for (int j = 0; j < 4; ++j) { acc[j][0] = 0ull; acc[j][1] = 0ull; }
        #pragma unroll 4
        for (int c4 = 0; c4 < 16; ++c4) {
            ulonglong2 wA[4], wB[4];
            #pragma unroll
            for (int j = 0; j < 4; ++j) {
                wA[j] = *(const ulonglong2*)&W2[tr + 16 * j][c4 * 4];
                wB[j] = *(const ulonglong2*)&W2[tr + 16 * j][c4 * 4 + 2];
            }
            #pragma unroll
            for (int cc = 0; cc < 4; ++cc) {
                ulonglong2 p2 = *(const ulonglong2*)&ph[c4 * 4 + cc][kq2 * 4];
                #pragma unroll
                for (int j = 0; j < 4; ++j) {
                    unsigned long long w2 =
                        (cc == 0) ? wA[j].x : (cc == 1) ? wA[j].y
                      : (cc == 2) ? wB[j].x : wB[j].y;
                    pfma(acc[j][0], w2, p2.x);
                    pfma(acc[j][1], w2, p2.y);
                }
            }
        }
        #pragma unroll
        for (int j = 0; j < 4; ++j) {
            float4 o4;
            punpack(acc[j][0], o4.x, o4.y);
            punpack(acc[j][1], o4.z, o4.w);
            atomicAdd((float4*)&g_Macc[(b0 + tr + 16 * j) * Kc + kq2 * 4], o4);
        }
    }

    // 2b: Nacc[v,k] += sum_b W2[b][v] * th[b][k];  v rows tr*4..tr*4+3
    {
        unsigned long long acc[4][2];
        #pragma unroll
        for (int j = 0; j < 4; ++j) { acc[j][0] = 0ull; acc[j][1] = 0ull; }
        #pragma unroll 8
        for (int c = 0; c < 64; ++c) {
            ulonglong2 t2 = *(const ulonglong2*)&th[c][kq2 * 4];
            ulonglong2 wA = *(const ulonglong2*)&W2[c][tr * 4];
            ulonglong2 wB = *(const ulonglong2*)&W2[c][tr * 4 + 2];
            pfma(acc[0][0], wA.x, t2.x); pfma(acc[0][1], wA.x, t2.y);
            pfma(acc[1][0], wA.y, t2.x); pfma(acc[1][1], wA.y, t2.y);
            pfma(acc[2][0], wB.x, t2.x); pfma(acc[2][1], wB.x, t2.y);
            pfma(acc[3][0], wB.y, t2.x); pfma(acc[3][1], wB.y, t2.y);
        }
        #pragma unroll
        for (int j = 0; j < 4; ++j) {
            float4 o4;
            punpack(acc[j][0], o4.x, o4.y);
            punpack(acc[j][1], o4.z, o4.w);
            atomicAdd((float4*)&g_Nacc[(v0 + tr * 4 + j) * Kc + kq2 * 4], o4);
        }
    }

    // ---- bar1 ARRIVE; prefetch pure-input epilogue loads during skew ----
    unsigned ep1 = bar_arrive(1);

    int gid = rank * 256 + t;                 // 0..65535 == VK/4
    float4 pb = ((const float4*)beta)[gid];   // inputs: safe pre-wait
    float4 pe = ((const float4*)expn)[gid];
    float4 pem = make_float4(0.f, 0.f, 0.f, 0.f);
    if (gid < BK / 4) {
        int d = (int)idxw[((gid * 4) >> 6) * stride];
        pem = ((const float4*)expm)[d * 16 + (gid & 15)];
    }

    bar_wait(1, ep1);

    // ---- epilogue (L2-hot), accumulators read + self-reset ----
    float rho = g_rho, omr = 1.f - rho, rr2 = rho * g_ratio;
    const float4 z4 = make_float4(0.f, 0.f, 0.f, 0.f);

    {
        float4 n4 = ((const float4*)g_Nacc)[gid];
        float4 tn;
        tn.x = (pb.x + pe.x) * n4.x; tn.y = (pb.y + pe.y) * n4.y;
        tn.z = (pb.z + pe.z) * n4.z; tn.w = (pb.w + pe.w) * n4.w;
        ((float4*)g_Nacc)[gid] = z4;           // self-reset for next replay
        ((float4*)(out + OUT_TN))[gid] = tn;
        int c0 = OUT_NN + gid * 4;
        out[c0+0] = fmaf(omr, pe.x, rr2*tn.x);
        out[c0+1] = fmaf(omr, pe.y, rr2*tn.y);
        out[c0+2] = fmaf(omr, pe.z, rr2*tn.z);
        out[c0+3] = fmaf(omr, pe.w, rr2*tn.w);
    }

    if (gid < BK / 4) {                        // 4096 float4 units for TM/NM
        float4 t4 = ((const float4*)g_theta)[gid];
        float4 m4 = ((const float4*)g_Macc)[gid];
        float4 tm = make_float4(t4.x*m4.x, t4.y*m4.y, t4.z*m4.z, t4.w*m4.w);
        ((float4*)g_Macc)[gid] = z4;           // self-reset
        ((float4*)(out + OUT_TM))[gid] = tm;
        int c0 = OUT_NM + gid * 4;
        out[c0+0] = fmaf(omr, pem.x, rho*tm.x);
        out[c0+1] = fmaf(omr, pem.y, rho*tm.y);
        out[c0+2] = fmaf(omr, pem.z, rho*tm.z);
        out[c0+3] = fmaf(omr, pem.w, rho*tm.w);
    }

    if (rank == 0 && t < 64)
        g_denom[t] = 0.f;                      // self-reset
}

// ---------------------------------------------------------------------------
extern "C" void kernel_launch(void* const* d_in, const int* in_sizes, int n_in,
                              void* d_out, int out_size) {
    const int*          bow   = (const int*)d_in[0];
    const unsigned int* idxw  = (const unsigned int*)d_in[1];
    const float*        alpha = (const float*)d_in[2];
    const float*        pi    = (const float*)d_in[3];
    const float*        expm  = (const float*)d_in[4];
    const float*        beta  = (const float*)d_in[5];
    const float*        expn  = (const float*)d_in[6];
    const int*          iterp = (const int*)d_in[7];
    const int*          cmp   = (const int*)d_in[8];
    const int*          bcp   = (const int*)d_in[9];
    float* out = (float*)d_out;

    static int smem_set = 0;
    const int k_smem = 256 * 68 * 4 + 64 * 66 * 8;  // 69632 + 33792 = 103424
    if (!smem_set) {
        cudaFuncSetAttribute(mono, cudaFuncAttributeMaxDynamicSharedMemorySize, k_smem);
        smem_set = 1;
    }

    dim3 g(Vc / 64, Bc / 64);   // 256 blocks, all co-resident (2/SM)
    mono<<<g, 256, k_smem>>>(bow, idxw, alpha, pi, expm, beta, expn,
                             iterp, cmp, bcp, out);
}

// round 17
// speedup vs baseline: 1.1480x; 1.1480x over previous
#include <cuda_runtime.h>
#include <math.h>

#define Bc 256
#define Vc 4096
#define Kc 64
#define MINIf 1e-6f

#define VK (Vc*Kc)             /* 262144 */
#define BK (Bc*Kc)             /* 16384  */
#define OUT_TN 0
#define OUT_TM VK
#define OUT_QZ (VK+BK)
#define OUT_NN (VK+BK+1)
#define OUT_NM (VK+BK+1+VK)

#define NBLK 256

// device scratch — float4-accessed arrays explicitly 16B-aligned
__device__ __align__(16) float g_theta[BK];   // theta' published by x==0 blocks
__device__ __align__(16) float g_Nacc[VK];    // self-reset in epilogue
__device__ __align__(16) float g_Macc[BK];    // self-reset in epilogue
__device__ __align__(16) float g_denom[Kc];   // self-reset post-bar1
__device__ unsigned g_barcnt[2];              // monotone epoch counters
__device__ unsigned g_barrel[2];
__device__ float g_rho;
__device__ float g_ratio;

// ---- packed f32x2 helpers (Blackwell FFMA2) --------------------------------
__device__ __forceinline__ void pfma(unsigned long long& acc,
                                     unsigned long long a, unsigned long long b) {
    asm("fma.rn.f32x2 %0, %1, %2, %0;" : "+l"(acc) : "l"(a), "l"(b));
}
__device__ __forceinline__ float psum(unsigned long long v) {
    return __uint_as_float((unsigned)v) + __uint_as_float((unsigned)(v >> 32));
}
__device__ __forceinline__ unsigned long long fpack2(float lo, float hi) {
    unsigned long long r;
    asm("mov.b64 %0, {%1, %2};" : "=l"(r) : "f"(lo), "f"(hi));
    return r;
}
__device__ __forceinline__ void punpack(unsigned long long v, float& lo, float& hi) {
    lo = __uint_as_float((unsigned)v);
    hi = __uint_as_float((unsigned)(v >> 32));
}

// ---- split grid barrier (epoch-monotone; replay-safe) -----------------------
__device__ __forceinline__ unsigned bar_arrive(int id) {
    __syncthreads();
    __shared__ unsigned s_ep[2];
    if (threadIdx.x == 0) {
        __threadfence();
        unsigned arrive = atomicAdd(&g_barcnt[id], 1u) + 1u;
        unsigned epoch = (arrive + NBLK - 1u) / NBLK;
        if (arrive == epoch * NBLK)
            atomicAdd(&g_barrel[id], 1u);
        s_ep[id] = epoch;
    }
    __syncthreads();
    return s_ep[id];
}
__device__ __forceinline__ void bar_wait(int id, unsigned epoch) {
    if (threadIdx.x == 0) {
        while (atomicAdd(&g_barrel[id], 0u) < epoch) __nanosleep(64);
    }
    __syncthreads();
}

// ---------------------------------------------------------------------------
__global__ void __launch_bounds__(256, 2)
mono(const int* __restrict__ bow,
     const unsigned int* __restrict__ idxw,
     const float* __restrict__ alpha,
     const float* __restrict__ pi,
     const float* __restrict__ expm,
     const float* __restrict__ beta,
     const float* __restrict__ expn,
     const int* __restrict__ iterp,
     const int* __restrict__ cmp,
     const int* __restrict__ bcp,
     float* __restrict__ out) {
    extern __shared__ float sm3[];
    float (*th)[68]  = (float(*)[68])(sm3);
    float (*thL)[68] = (float(*)[68])(sm3 + 64 * 68);   // becomes Wt in phase 2
    float (*ph)[68]  = (float(*)[68])(sm3 + 128 * 68);
    float (*phL)[68] = (float(*)[68])(sm3 + 192 * 68);
    float (*Wt)[68]  = thL;

    __shared__ __align__(16) float red[16][68];
    __shared__ __align__(16) float srd[64];
    __shared__ __align__(16) float sld[64];
    __shared__ float ered[8];
    __shared__ int s_nz;

    int t = threadIdx.x;
    int rank = blockIdx.y * 64 + blockIdx.x;
    int v0 = blockIdx.x * 64;
    int b0 = blockIdx.y * 64;
    int tv = t & 15;       // v_local = tv + 16*vi
    int tb = t >> 4;       // b_local = tb + 16*bi

    // ---- phase 0: bow prefetch + denominator partial + scalars ----
    int cnt[4][4];
    #pragma unroll
    for (int bi = 0; bi < 4; ++bi)
        #pragma unroll
        for (int vi = 0; vi < 4; ++vi)
            cnt[bi][vi] = bow[(b0 + tb + 16 * bi) * Vc + v0 + tv + 16 * vi];

    if (t == 0) s_nz = 0;
    {
        int cq = t & 15, rr = t >> 4;
        int vp = rank * 16;
        float4 db = ((const float4*)beta)[(vp + rr) * 16 + cq];
        float4 de = ((const float4*)expn)[(vp + rr) * 16 + cq];
        __syncthreads();                       // s_nz init visible
        if (t < 128 && idxw[2 * t + 1] != 0u) atomicOr(&s_nz, 1);
        float4 a;
        a.x = db.x + de.x; a.y = db.y + de.y;
        a.z = db.z + de.z; a.w = db.w + de.w;
        *(float4*)&red[rr][cq * 4] = a;
        __syncthreads();
        if (t < 64) {
            float s = 0.f;
            #pragma unroll
            for (int r2 = 0; r2 < 16; ++r2) s += red[r2][t];
            atomicAdd(&g_denom[t], s);
        }
        if (rank == 255 && t == 0) {
            g_rho   = 1.f / powf((float)(iterp[0] + 5), 0.9f);
            g_ratio = (float)cmp[0] / (float)bcp[0];
            out[OUT_QZ] = 0.f;
        }
    }
    int stride = s_nz ? 1 : 2;    // int32 vs int64 batch_indices

    // ---- bar0 ARRIVE early (skew absorbed by the log-heavy fill below) ----
    unsigned ep0 = bar_arrive(0);

    // tile fill (NO denominator needed)
    #pragma unroll
    for (int j = 0; j < 4; ++j) {
        int i = j * 256 + t;
        int r = i >> 4, cq = i & 15;
        float4 b4 = ((const float4*)beta)[(v0 + r) * 16 + cq];
        float4 e4 = ((const float4*)expn)[(v0 + r) * 16 + cq];
        float4 p;
        p.x = b4.x + e4.x; p.y = b4.y + e4.y;
        p.z = b4.z + e4.z; p.w = b4.w + e4.w;
        float4 pl;
        pl.x = p.x * __logf(p.x);
        pl.y = p.y * __logf(p.y);
        pl.z = p.z * __logf(p.z);
        pl.w = p.w * __logf(p.w);
        *(float4*)&ph [r][cq * 4] = p;
        *(float4*)&phL[r][cq * 4] = pl;
        int d = (int)idxw[(b0 + r) * stride];
        float4 al = ((const float4*)alpha)[cq];
        float4 pp = ((const float4*)pi   )[d * 16 + cq];
        float4 em = ((const float4*)expm )[d * 16 + cq];
        float4 traw, tl;
        traw.x = fmaf(al.x, pp.x, em.x);
        traw.y = fmaf(al.y, pp.y, em.y);
        traw.z = fmaf(al.z, pp.z, em.z);
        traw.w = fmaf(al.w, pp.w, em.w);
        tl.x = traw.x * __logf(traw.x);
        tl.y = traw.y * __logf(traw.y);
        tl.z = traw.z * __logf(traw.z);
        tl.w = traw.w * __logf(traw.w);
        *(float4*)&th [r][cq * 4] = traw;
        *(float4*)&thL[r][cq * 4] = tl;
    }

    // ---- bar0 WAIT ----
    bar_wait(0, ep0);

    if (t < 64) {
        float d = g_denom[t];
        srd[t] = __fdividef(1.f, d);
        sld[t] = __logf(d);
    }
    __syncthreads();

    // scale theta tiles: th' = traw*rd ; thL' = (trawL - traw*ld)*rd
    #pragma unroll
    for (int j = 0; j < 4; ++j) {
        int i = j * 256 + t;
        int r = i >> 4, cq = i & 15;
        float4 tp  = *(const float4*)&th [r][cq * 4];
        float4 tlp = *(const float4*)&thL[r][cq * 4];
        float4 rd = *(const float4*)&srd[cq * 4];
        float4 ld = *(const float4*)&sld[cq * 4];
        float4 tt, tl;
        tt.x = tp.x * rd.x; tt.y = tp.y * rd.y;
        tt.z = tp.z * rd.z; tt.w = tp.w * rd.w;
        tl.x = (tlp.x - tp.x * ld.x) * rd.x;
        tl.y = (tlp.y - tp.y * ld.y) * rd.y;
        tl.z = (tlp.z - tp.z * ld.z) * rd.z;
        tl.w = (tlp.w - tp.w * ld.w) * rd.w;
        *(float4*)&th [r][cq * 4] = tt;
        *(float4*)&thL[r][cq * 4] = tl;
    }
    // theta' publish hoisted out of the hot loop (only 4 of 256 blocks)
    if (blockIdx.x == 0) {
        #pragma unroll
        for (int j = 0; j < 4; ++j) {
            int i = j * 256 + t;
            int r = i >> 4, cq = i & 15;
            ((float4*)g_theta)[(b0 + r) * 16 + cq] =
                *(const float4*)&th[r][cq * 4];
        }
    }
    __syncthreads();

    // ---- phase 1: S/A GEMM (fully unrolled: immediate LDS offsets) ----
    unsigned long long S2[4][4], A2[4][4];
    #pragma unroll
    for (int bi = 0; bi < 4; ++bi)
        #pragma unroll
        for (int vi = 0; vi < 4; ++vi) { S2[bi][vi] = 0ull; A2[bi][vi] = 0ull; }

    #pragma unroll
    for (int kq = 0; kq < 16; ++kq) {
        ulonglong2 P[4], Q[4];
        #pragma unroll
        for (int vi = 0; vi < 4; ++vi) {
            P[vi] = *(const ulonglong2*)&ph [tv + 16 * vi][kq * 4];
            Q[vi] = *(const ulonglong2*)&phL[tv + 16 * vi][kq * 4];
        }
        #pragma unroll
        for (int bi = 0; bi < 4; ++bi) {
            ulonglong2 T = *(const ulonglong2*)&th [tb + 16 * bi][kq * 4];
            ulonglong2 L = *(const ulonglong2*)&thL[tb + 16 * bi][kq * 4];
            #pragma unroll
            for (int vi = 0; vi < 4; ++vi) {
                pfma(S2[bi][vi], T.x, P[vi].x);
                pfma(S2[bi][vi], T.y, P[vi].y);
                pfma(A2[bi][vi], L.x, P[vi].x);
                pfma(A2[bi][vi], L.y, P[vi].y);
                pfma(A2[bi][vi], T.x, Q[vi].x);
                pfma(A2[bi][vi], T.y, Q[vi].y);
            }
        }
    }

    // w, entropy (branchless mask)
    float wv[4][4];
    float ent = 0.f;
    #pragma unroll
    for (int bi = 0; bi < 4; ++bi) {
        #pragma unroll
        for (int vi = 0; vi < 4; ++vi) {
            float S = psum(S2[bi][vi]);
            float A = psum(A2[bi][vi]);
            float sp = S + MINIf;
            float r  = __fdividef(1.f, sp);
            int c = cnt[bi][vi];
            wv[bi][vi] = (float)c * r;
            float rm = (c > 0) ? r : 0.f;
            ent = fmaf(rm, A - S * __logf(sp), ent);
        }
    }

    #pragma unroll
    for (int o = 16; o; o >>= 1)
        ent += __shfl_xor_sync(0xFFFFFFFFu, ent, o);
    if ((t & 31) == 0) ered[t >> 5] = ent;

    __syncthreads();   // thL reads done; ered visible
    if (t == 0) {
        float s = 0.f;
        #pragma unroll
        for (int w = 0; w < 8; ++w) s += ered[w];
        atomicAdd(&out[OUT_QZ], s);
    }

    // stage W into smem (overwrites thL)
    #pragma unroll
    for (int bi = 0; bi < 4; ++bi)
        #pragma unroll
        for (int vi = 0; vi < 4; ++vi)
            Wt[tb + 16 * bi][tv + 16 * vi] = wv[bi][vi];
    __syncthreads();

    // ---- phase 2 ----
    int kq2 = t & 15;
    int tr  = t >> 4;

    // 2a: Macc[b, k] += sum_c Wt[b_local][c] * ph[c][k]
    {
        unsigned long long acc[4][2];
        #pragma unroll
        for (int j = 0; j < 4; ++j) { acc[j][0] = 0ull; acc[j][1] = 0ull; }
        #pragma unroll 4
        for (int c4 = 0; c4 < 16; ++c4) {
            float Wc[4][4];
            #pragma unroll
            for (int j = 0; j < 4; ++j) {
                float4 w4 = *(const float4*)&Wt[tr + 16 * j][c4 * 4];
                Wc[j][0] = w4.x; Wc[j][1] = w4.y;
                Wc[j][2] = w4.z; Wc[j][3] = w4.w;
            }
            #pragma unroll
            for (int cc = 0; cc < 4; ++cc) {
                ulonglong2 p2 = *(const ulonglong2*)&ph[c4 * 4 + cc][kq2 * 4];
                #pragma unroll
                for (int j = 0; j < 4; ++j) {
                    unsigned long long w2 = fpack2(Wc[j][cc], Wc[j][cc]);
                    pfma(acc[j][0], w2, p2.x);
                    pfma(acc[j][1], w2, p2.y);
                }
            }
        }
        #pragma unroll
        for (int j = 0; j < 4; ++j) {
            float4 o4;
            punpack(acc[j][0], o4.x, o4.y);
            punpack(acc[j][1], o4.z, o4.w);
            atomicAdd((float4*)&g_Macc[(b0 + tr + 16 * j) * Kc + kq2 * 4], o4);
        }
    }

    // 2b: Nacc[v, k] += sum_c Wt[c][v_local] * th[c][k]
    {
        unsigned long long acc[4][2];
        #pragma unroll
        for (int j = 0; j < 4; ++j) { acc[j][0] = 0ull; acc[j][1] = 0ull; }
        #pragma unroll 8
        for (int c = 0; c < 64; ++c) {
            ulonglong2 t2 = *(const ulonglong2*)&th[c][kq2 * 4];
            float4 w4 = *(const float4*)&Wt[c][tr * 4];
            unsigned long long w20 = fpack2(w4.x, w4.x);
            unsigned long long w21 = fpack2(w4.y, w4.y);
            unsigned long long w22 = fpack2(w4.z, w4.z);
            unsigned long long w23 = fpack2(w4.w, w4.w);
            pfma(acc[0][0], w20, t2.x); pfma(acc[0][1], w20, t2.y);
            pfma(acc[1][0], w21, t2.x); pfma(acc[1][1], w21, t2.y);
            pfma(acc[2][0], w22, t2.x); pfma(acc[2][1], w22, t2.y);
            pfma(acc[3][0], w23, t2.x); pfma(acc[3][1], w23, t2.y);
        }
        #pragma unroll
        for (int j = 0; j < 4; ++j) {
            float4 o4;
            punpack(acc[j][0], o4.x, o4.y);
            punpack(acc[j][1], o4.z, o4.w);
            atomicAdd((float4*)&g_Nacc[(v0 + tr * 4 + j) * Kc + kq2 * 4], o4);
        }
    }

    // ---- bar1 ARRIVE; prefetch pure-input epilogue loads during skew ----
    unsigned ep1 = bar_arrive(1);

    int gid = rank * 256 + t;                 // 0..65535 == VK/4
    float4 pb = ((const float4*)beta)[gid];   // inputs: safe pre-wait
    float4 pe = ((const float4*)expn)[gid];
    float4 pem = make_float4(0.f, 0.f, 0.f, 0.f);
    if (gid < BK / 4) {
        int d = (int)idxw[((gid * 4) >> 6) * stride];
        pem = ((const float4*)expm)[d * 16 + (gid & 15)];
    }

    bar_wait(1, ep1);

    // ---- epilogue (L2-hot), accumulators read + self-reset ----
    float rho = g_rho, omr = 1.f - rho, rr2 = rho * g_ratio;
    const float4 z4 = make_float4(0.f, 0.f, 0.f, 0.f);

    {
        float4 n4 = ((const float4*)g_Nacc)[gid];
        float4 tn;
        tn.x = (pb.x + pe.x) * n4.x; tn.y = (pb.y + pe.y) * n4.y;
        tn.z = (pb.z + pe.z) * n4.z; tn.w = (pb.w + pe.w) * n4.w;
        ((float4*)g_Nacc)[gid] = z4;           // self-reset for next replay
        ((float4*)(out + OUT_TN))[gid] = tn;
        int c0 = OUT_NN + gid * 4;
        out[c0+0] = fmaf(omr, pe.x, rr2*tn.x);
        out[c0+1] = fmaf(omr, pe.y, rr2*tn.y);
        out[c0+2] = fmaf(omr, pe.z, rr2*tn.z);
        out[c0+3] = fmaf(omr, pe.w, rr2*tn.w);
    }

    if (gid < BK / 4) {                        // 4096 float4 units for TM/NM
        float4 t4 = ((const float4*)g_theta)[gid];
        float4 m4 = ((const float4*)g_Macc)[gid];
        float4 tm = make_float4(t4.x*m4.x, t4.y*m4.y, t4.z*m4.z, t4.w*m4.w);
        ((float4*)g_Macc)[gid] = z4;           // self-reset
        ((float4*)(out + OUT_TM))[gid] = tm;
        int c0 = OUT_NM + gid * 4;
        out[c0+0] = fmaf(omr, pem.x, rho*tm.x);
        out[c0+1] = fmaf(omr, pem.y, rho*tm.y);
        out[c0+2] = fmaf(omr, pem.z, rho*tm.z);
        out[c0+3] = fmaf(omr, pem.w, rho*tm.w);
    }

    if (rank == 0 && t < 64)
        g_denom[t] = 0.f;                      // self-reset
}

// ---------------------------------------------------------------------------
extern "C" void kernel_launch(void* const* d_in, const int* in_sizes, int n_in,
                              void* d_out, int out_size) {
    const int*          bow   = (const int*)d_in[0];
    const unsigned int* idxw  = (const unsigned int*)d_in[1];
    const float*        alpha = (const float*)d_in[2];
    const float*        pi    = (const float*)d_in[3];
    const float*        expm  = (const float*)d_in[4];
    const float*        beta  = (const float*)d_in[5];
    const float*        expn  = (const float*)d_in[6];
    const int*          iterp = (const int*)d_in[7];
    const int*          cmp   = (const int*)d_in[8];
    const int*          bcp   = (const int*)d_in[9];
    float* out = (float*)d_out;

    static int smem_set = 0;
    const int k_smem = 256 * 68 * 4;  // 69632 bytes dynamic
    if (!smem_set) {
        cudaFuncSetAttribute(mono, cudaFuncAttributeMaxDynamicSharedMemorySize, k_smem);
        smem_set = 1;
    }

    dim3 g(Vc / 64, Bc / 64);   // 256 blocks, all co-resident (2/SM)
    mono<<<g, 256, k_smem>>>(bow, idxw, alpha, pi, expm, beta, expn,
                             iterp, cmp, bcp, out);
}